// round 6
// baseline (speedup 1.0000x reference)
#include <cuda_runtime.h>
#include <cuda_fp16.h>
#include <math.h>
#include <stdint.h>

#define NN 50000
#define EE 800000
#define DD 64
#define HH 8

// ---------------- scratch (static device globals; no allocation) ----------------
__device__ float  g_h[NN * DD];      // node features fp32 (layer input / ping)
__device__ __half g_hph[NN * DD];    // projected features, half (edge gather)
__device__ float  g_ai[NN * HH];     // per-node att dot, dst half (fp32)
__device__ __half g_ajh[NN * HH];    // per-node att dot, src half (fp16)
__device__ int    g_deg[NN];
__device__ int    g_rowptr[NN + 1];
__device__ int    g_cursor[NN];
__device__ int    g_csrc[EE];        // CSR-by-dst: source node per slot
__device__ int    g_bsum[64];

// ---------------- CSR build ----------------
__global__ void k_hist(const int* __restrict__ dst) {
    int e = blockIdx.x * blockDim.x + threadIdx.x;
    if (e < EE) atomicAdd(&g_deg[dst[e]], 1);
}

__global__ void __launch_bounds__(1024) k_scan1() {
    __shared__ int ws[32];
    int i = blockIdx.x * 1024 + threadIdx.x;
    int lane = threadIdx.x & 31, w = threadIdx.x >> 5;
    int x = (i < NN) ? g_deg[i] : 0;
    int v = x;
#pragma unroll
    for (int o = 1; o < 32; o <<= 1) {
        int t = __shfl_up_sync(0xffffffffu, v, o);
        if (lane >= o) v += t;
    }
    if (lane == 31) ws[w] = v;
    __syncthreads();
    if (w == 0) {
        int t = ws[lane];
#pragma unroll
        for (int o = 1; o < 32; o <<= 1) {
            int u = __shfl_up_sync(0xffffffffu, t, o);
            if (lane >= o) t += u;
        }
        ws[lane] = t;
    }
    __syncthreads();
    int off = (w > 0) ? ws[w - 1] : 0;
    int incl = v + off;
    if (i < NN) g_rowptr[i] = incl - x;           // exclusive within block
    if (threadIdx.x == 1023) g_bsum[blockIdx.x] = incl;  // inclusive block total
}

// adds block-prefix (computed in-block from g_bsum) and inits cursor
__global__ void __launch_bounds__(256) k_scan3() {
    __shared__ int carry_s;
    int chunkId = (blockIdx.x * 256) >> 10;       // which scan1 block we're in
    if (threadIdx.x < 32) {
        int v = 0;
        if (threadIdx.x < chunkId) v = g_bsum[threadIdx.x];
        int b2 = threadIdx.x + 32;
        if (b2 < chunkId) v += g_bsum[b2];
#pragma unroll
        for (int o = 16; o > 0; o >>= 1) v += __shfl_xor_sync(0xffffffffu, v, o);
        if (threadIdx.x == 0) carry_s = v;
    }
    __syncthreads();
    int i = blockIdx.x * 256 + threadIdx.x;
    if (i < NN) {
        int r = g_rowptr[i] + carry_s;
        g_rowptr[i] = r;
        g_cursor[i] = r;
    }
    if (i == 0) g_rowptr[NN] = EE;
}

__global__ void k_scatter(const int* __restrict__ src, const int* __restrict__ dst) {
    int e = blockIdx.x * blockDim.x + threadIdx.x;
    if (e < EE) {
        int pos = atomicAdd(&g_cursor[dst[e]], 1);
        g_csrc[pos] = src[e];
    }
}

// ---------------- split-fp16 tensor GEMM: C[N,64] = A[N,64] @ W[64,64] + bias ----------------
// Markidis split: A=Ah+Al, W=Wh+Wl (fp16); acc += Ah*Wh + Al*Wh + Ah*Wl (fp32).
// Effective precision ~2^-22 ~= fp32. Block 128 thr / 64 rows; warp tile m16 n64 k64.
// att mode: writes half hp + fused per-head attention dots ai (fp32) / aj (fp16).
// relu mode: writes fp32 Cf (input embedding).
__device__ __forceinline__ uint32_t smem_u32(const void* p) {
    return (uint32_t)__cvta_generic_to_shared(p);
}

#define LDSM_X4(r0, r1, r2, r3, addr) \
    asm volatile("ldmatrix.sync.aligned.m8n8.x4.shared.b16 {%0,%1,%2,%3}, [%4];" \
        : "=r"(r0), "=r"(r1), "=r"(r2), "=r"(r3) : "r"(addr))

#define LDSM_X4_T(r0, r1, r2, r3, addr) \
    asm volatile("ldmatrix.sync.aligned.m8n8.x4.trans.shared.b16 {%0,%1,%2,%3}, [%4];" \
        : "=r"(r0), "=r"(r1), "=r"(r2), "=r"(r3) : "r"(addr))

#define MMA16816(c, a0, a1, a2, a3, b0, b1) \
    asm volatile("mma.sync.aligned.m16n8k16.row.col.f32.f16.f16.f32 " \
        "{%0,%1,%2,%3}, {%4,%5,%6,%7}, {%8,%9}, {%0,%1,%2,%3};" \
        : "+f"(c[0]), "+f"(c[1]), "+f"(c[2]), "+f"(c[3]) \
        : "r"(a0), "r"(a1), "r"(a2), "r"(a3), "r"(b0), "r"(b1))

#define SMS 72   // smem row stride in halves (64 + 8 pad)

__device__ __forceinline__ void split2(float a, __half& hi, __half& lo) {
    hi = __float2half_rn(a);
    lo = __float2half_rn(a - __half2float(hi));
}

__global__ void __launch_bounds__(128) k_gemm_s(const float* __restrict__ A,
                                                const float* __restrict__ W,
                                                const float* __restrict__ bias,
                                                float* __restrict__ Cf,
                                                __half* __restrict__ Ch,
                                                int do_relu,
                                                const float* __restrict__ att) {
    __shared__ __half Ash[64 * SMS], Asl[64 * SMS];
    __shared__ __half Bsh[64 * SMS], Bsl[64 * SMS];
    int tid = threadIdx.x;
    int base = blockIdx.x * 64;
#pragma unroll
    for (int i = 0; i < 4; i++) {
        int chunk = tid + i * 128;            // 0..511
        int r = chunk >> 3, c = (chunk & 7) * 8;
        float4 w0 = *(const float4*)(W + r * 64 + c);
        float4 w1 = *(const float4*)(W + r * 64 + c + 4);
        const float* wv = (const float*)&w0;
#pragma unroll
        for (int q = 0; q < 4; q++) {
            __half hi, lo;
            split2(wv[q], hi, lo);
            Bsh[r * SMS + c + q] = hi; Bsl[r * SMS + c + q] = lo;
        }
        wv = (const float*)&w1;
#pragma unroll
        for (int q = 0; q < 4; q++) {
            __half hi, lo;
            split2(wv[q], hi, lo);
            Bsh[r * SMS + c + 4 + q] = hi; Bsl[r * SMS + c + 4 + q] = lo;
        }
        int gr = base + r;
        float4 a0 = make_float4(0.f, 0.f, 0.f, 0.f), a1 = a0;
        if (gr < NN) {
            a0 = *(const float4*)(A + (size_t)gr * 64 + c);
            a1 = *(const float4*)(A + (size_t)gr * 64 + c + 4);
        }
        const float* av = (const float*)&a0;
#pragma unroll
        for (int q = 0; q < 4; q++) {
            __half hi, lo;
            split2(av[q], hi, lo);
            Ash[r * SMS + c + q] = hi; Asl[r * SMS + c + q] = lo;
        }
        av = (const float*)&a1;
#pragma unroll
        for (int q = 0; q < 4; q++) {
            __half hi, lo;
            split2(av[q], hi, lo);
            Ash[r * SMS + c + 4 + q] = hi; Asl[r * SMS + c + 4 + q] = lo;
        }
    }
    __syncthreads();

    int warp = tid >> 5, lane = tid & 31;
    int m0 = warp * 16;
    float acc[8][4];
#pragma unroll
    for (int n = 0; n < 8; n++)
#pragma unroll
        for (int q = 0; q < 4; q++) acc[n][q] = 0.f;

#pragma unroll
    for (int kk = 0; kk < 4; kk++) {
        uint32_t ah0, ah1, ah2, ah3, al0, al1, al2, al3;
        int aoff = (m0 + (lane & 15)) * SMS + kk * 16 + (lane >> 4) * 8;
        LDSM_X4(ah0, ah1, ah2, ah3, smem_u32(Ash + aoff));
        LDSM_X4(al0, al1, al2, al3, smem_u32(Asl + aoff));
#pragma unroll
        for (int np = 0; np < 4; np++) {
            uint32_t bh0, bh1, bh2, bh3, bl0, bl1, bl2, bl3;
            int boff = (kk * 16 + (lane & 15)) * SMS + np * 16 + (lane >> 4) * 8;
            LDSM_X4_T(bh0, bh1, bh2, bh3, smem_u32(Bsh + boff));
            LDSM_X4_T(bl0, bl1, bl2, bl3, smem_u32(Bsl + boff));
            MMA16816(acc[2 * np],     ah0, ah1, ah2, ah3, bh0, bh1);
            MMA16816(acc[2 * np],     al0, al1, al2, al3, bh0, bh1);
            MMA16816(acc[2 * np],     ah0, ah1, ah2, ah3, bl0, bl1);
            MMA16816(acc[2 * np + 1], ah0, ah1, ah2, ah3, bh2, bh3);
            MMA16816(acc[2 * np + 1], al0, al1, al2, al3, bh2, bh3);
            MMA16816(acc[2 * np + 1], ah0, ah1, ah2, ah3, bl2, bl3);
        }
    }

    int qr = lane >> 2, qc = (lane & 3) * 2;
    int r0 = base + m0 + qr, r1 = r0 + 8;
    const bool do_att = (att != nullptr);
    float pi0[8], pj0[8], pi1[8], pj1[8];
#pragma unroll
    for (int n = 0; n < 8; n++) {
        int col = n * 8 + qc;
        float2 bb = *(const float2*)(bias + col);
        float x0 = acc[n][0] + bb.x, y0 = acc[n][1] + bb.y;
        float x1 = acc[n][2] + bb.x, y1 = acc[n][3] + bb.y;
        if (do_att) {
            // head index == n; this thread covers cols qc, qc+1 of head n
            float ci0 = att[n * 16 + qc],     ci1 = att[n * 16 + qc + 1];
            float cj0 = att[n * 16 + 8 + qc], cj1 = att[n * 16 + 8 + qc + 1];
            pi0[n] = x0 * ci0 + y0 * ci1;  pj0[n] = x0 * cj0 + y0 * cj1;
            pi1[n] = x1 * ci0 + y1 * ci1;  pj1[n] = x1 * cj0 + y1 * cj1;
            if (r0 < NN) *(__half2*)(Ch + (size_t)r0 * 64 + col) = __floats2half2_rn(x0, y0);
            if (r1 < NN) *(__half2*)(Ch + (size_t)r1 * 64 + col) = __floats2half2_rn(x1, y1);
        } else {
            if (do_relu) {
                x0 = fmaxf(x0, 0.f); y0 = fmaxf(y0, 0.f);
                x1 = fmaxf(x1, 0.f); y1 = fmaxf(y1, 0.f);
            }
            if (r0 < NN) *(float2*)(Cf + (size_t)r0 * 64 + col) = make_float2(x0, y0);
            if (r1 < NN) *(float2*)(Cf + (size_t)r1 * 64 + col) = make_float2(x1, y1);
        }
    }
    if (do_att) {
        // quad reduce (lanes differing in lane&3 hold the other cols of each head)
#pragma unroll
        for (int n = 0; n < 8; n++) {
            pi0[n] += __shfl_xor_sync(0xffffffffu, pi0[n], 1);
            pi0[n] += __shfl_xor_sync(0xffffffffu, pi0[n], 2);
            pj0[n] += __shfl_xor_sync(0xffffffffu, pj0[n], 1);
            pj0[n] += __shfl_xor_sync(0xffffffffu, pj0[n], 2);
            pi1[n] += __shfl_xor_sync(0xffffffffu, pi1[n], 1);
            pi1[n] += __shfl_xor_sync(0xffffffffu, pi1[n], 2);
            pj1[n] += __shfl_xor_sync(0xffffffffu, pj1[n], 1);
            pj1[n] += __shfl_xor_sync(0xffffffffu, pj1[n], 2);
        }
        if ((lane & 3) == 0) {
            if (r0 < NN) {
                *(float4*)(g_ai + r0 * 8)     = make_float4(pi0[0], pi0[1], pi0[2], pi0[3]);
                *(float4*)(g_ai + r0 * 8 + 4) = make_float4(pi0[4], pi0[5], pi0[6], pi0[7]);
                __half2* aj = (__half2*)(g_ajh + r0 * 8);
                aj[0] = __floats2half2_rn(pj0[0], pj0[1]);
                aj[1] = __floats2half2_rn(pj0[2], pj0[3]);
                aj[2] = __floats2half2_rn(pj0[4], pj0[5]);
                aj[3] = __floats2half2_rn(pj0[6], pj0[7]);
            }
            if (r1 < NN) {
                *(float4*)(g_ai + r1 * 8)     = make_float4(pi1[0], pi1[1], pi1[2], pi1[3]);
                *(float4*)(g_ai + r1 * 8 + 4) = make_float4(pi1[4], pi1[5], pi1[6], pi1[7]);
                __half2* aj = (__half2*)(g_ajh + r1 * 8);
                aj[0] = __floats2half2_rn(pj1[0], pj1[1]);
                aj[1] = __floats2half2_rn(pj1[2], pj1[3]);
                aj[2] = __floats2half2_rn(pj1[4], pj1[5]);
                aj[3] = __floats2half2_rn(pj1[6], pj1[7]);
            }
        }
    }
}

// ---------------- fused edge softmax + aggregation + ELU + LayerNorm ----------------
// One warp per destination node. Lane l owns cols (2l,2l+1), head h = l>>2.
// Single-pass shift-free softmax; src indices preloaded coalesced + shuffled;
// 4-way unrolled gathers (fp16 features + fp16 aj). Output fp32.
__global__ void __launch_bounds__(256) k_edge(const float* __restrict__ ob,
                                              const float* __restrict__ lg,
                                              const float* __restrict__ lb,
                                              float* __restrict__ out) {
    int n = (blockIdx.x * blockDim.x + threadIdx.x) >> 5;
    int lane = threadIdx.x & 31;
    if (n >= NN) return;
    int e0 = __ldg(&g_rowptr[n]), e1 = __ldg(&g_rowptr[n + 1]);
    int h = lane >> 2;
    float aih = __ldg(&g_ai[n * 8 + h]);

    float s = 0.f, ax = 0.f, ay = 0.f;
    const __half2* hp2 = (const __half2*)g_hph;
    for (int cb = e0; cb < e1; cb += 32) {
        int idx = cb + lane;
        int pre = (idx < e1) ? __ldg(&g_csrc[idx]) : 0;
        int cnt = min(32, e1 - cb);
        int j = 0;
        for (; j + 4 <= cnt; j += 4) {
            int s0 = __shfl_sync(0xffffffffu, pre, j);
            int s1 = __shfl_sync(0xffffffffu, pre, j + 1);
            int s2 = __shfl_sync(0xffffffffu, pre, j + 2);
            int s3 = __shfl_sync(0xffffffffu, pre, j + 3);
            float b0 = __half2float(__ldg(&g_ajh[s0 * 8 + h]));
            float b1 = __half2float(__ldg(&g_ajh[s1 * 8 + h]));
            float b2 = __half2float(__ldg(&g_ajh[s2 * 8 + h]));
            float b3 = __half2float(__ldg(&g_ajh[s3 * 8 + h]));
            __half2 u0 = __ldg(&hp2[(size_t)s0 * 32 + lane]);
            __half2 u1 = __ldg(&hp2[(size_t)s1 * 32 + lane]);
            __half2 u2 = __ldg(&hp2[(size_t)s2 * 32 + lane]);
            __half2 u3 = __ldg(&hp2[(size_t)s3 * 32 + lane]);
            float2 v0 = __half22float2(u0);
            float2 v1 = __half22float2(u1);
            float2 v2 = __half22float2(u2);
            float2 v3 = __half22float2(u3);
            float a0 = aih + b0; a0 = fmaxf(a0, 0.2f * a0); float w0 = __expf(a0);
            float a1 = aih + b1; a1 = fmaxf(a1, 0.2f * a1); float w1 = __expf(a1);
            float a2 = aih + b2; a2 = fmaxf(a2, 0.2f * a2); float w2 = __expf(a2);
            float a3 = aih + b3; a3 = fmaxf(a3, 0.2f * a3); float w3 = __expf(a3);
            s += w0 + w1 + w2 + w3;
            ax += v0.x * w0 + v1.x * w1 + v2.x * w2 + v3.x * w3;
            ay += v0.y * w0 + v1.y * w1 + v2.y * w2 + v3.y * w3;
        }
        for (; j < cnt; j++) {
            int sj = __shfl_sync(0xffffffffu, pre, j);
            float b = __half2float(__ldg(&g_ajh[sj * 8 + h]));
            float2 v = __half22float2(__ldg(&hp2[(size_t)sj * 32 + lane]));
            float a = aih + b; a = fmaxf(a, 0.2f * a); float w = __expf(a);
            s += w;
            ax += v.x * w;
            ay += v.y * w;
        }
    }

    float inv = 1.f / (s + 1e-16f);
    float vx = ax * inv + ob[2 * lane];
    float vy = ay * inv + ob[2 * lane + 1];
    vx = vx > 0.f ? vx : expm1f(vx);          // ELU
    vy = vy > 0.f ? vy : expm1f(vy);

    float sum = vx + vy, sq = vx * vx + vy * vy;
#pragma unroll
    for (int o = 16; o > 0; o >>= 1) {
        sum += __shfl_xor_sync(0xffffffffu, sum, o);
        sq  += __shfl_xor_sync(0xffffffffu, sq, o);
    }
    float mu = sum * (1.f / 64.f);
    float var = sq * (1.f / 64.f) - mu * mu;
    float rstd = rsqrtf(var + 1e-5f);
    float2 o2;
    o2.x = (vx - mu) * rstd * lg[2 * lane] + lb[2 * lane];
    o2.y = (vy - mu) * rstd * lg[2 * lane + 1] + lb[2 * lane + 1];
    ((float2*)out)[(size_t)n * 32 + lane] = o2;
}

// ---------------- launch ----------------
extern "C" void kernel_launch(void* const* d_in, const int* in_sizes, int n_in,
                              void* d_out, int out_size) {
    const float* x        = (const float*)d_in[0];
    const int*   ei       = (const int*)  d_in[1];
    const float* W_in     = (const float*)d_in[2];
    const float* b_in     = (const float*)d_in[3];
    const float* lin_w    = (const float*)d_in[4];
    const float* lin_b    = (const float*)d_in[5];
    const float* att      = (const float*)d_in[6];
    const float* out_bias = (const float*)d_in[7];
    const float* ln_g     = (const float*)d_in[8];
    const float* ln_b     = (const float*)d_in[9];
    float* out = (float*)d_out;
    const int* srcp = ei;        // edge_index[0]
    const int* dstp = ei + EE;   // edge_index[1]
    (void)n_in; (void)in_sizes; (void)out_size;

    void* p;
    cudaGetSymbolAddress(&p, g_h);    float*  ph   = (float*)p;
    cudaGetSymbolAddress(&p, g_hph);  __half* phph = (__half*)p;
    cudaGetSymbolAddress(&p, g_deg);
    cudaMemsetAsync(p, 0, NN * sizeof(int));

    // CSR by dst
    const int nsb = (NN + 1023) / 1024;   // 49
    k_hist   <<<(EE + 255) / 256, 256>>>(dstp);
    k_scan1  <<<nsb, 1024>>>();
    k_scan3  <<<(NN + 255) / 256, 256>>>();
    k_scatter<<<(EE + 255) / 256, 256>>>(srcp, dstp);

    int gblocks = (NN + 63) / 64;
    // input embedding: h = relu(x @ W_in + b_in), fp32
    k_gemm_s<<<gblocks, 128>>>(x, W_in, b_in, ph, nullptr, 1, nullptr);

    for (int l = 0; l < 5; l++) {
        k_gemm_s<<<gblocks, 128>>>(ph, lin_w + l * 64 * 64, lin_b + l * 64,
                                   nullptr, phph, 0, att + l * 128);
        k_edge<<<(NN + 7) / 8, 256>>>(out_bias + l * 64, ln_g + l * 64, ln_b + l * 64,
                                      (l == 4) ? out : ph);
    }
}

// round 9
// speedup vs baseline: 1.1141x; 1.1141x over previous
#include <cuda_runtime.h>
#include <cuda_fp16.h>
#include <math.h>
#include <stdint.h>

#define NN 50000
#define EE 800000
#define DD 64
#define HH 8

// ---------------- scratch (static device globals; no allocation) ----------------
__device__ float  g_h[NN * DD];      // node features fp32 (layer input / ping)
__device__ __half g_hph[NN * DD];    // projected features, half (edge gather)
__device__ float  g_ai[NN * HH];     // per-node att dot, dst half (fp32)
__device__ __half g_ajh[NN * HH];    // per-node att dot, src half (fp16)
__device__ int    g_deg[NN];
__device__ int    g_rowptr[NN + 1];
__device__ int    g_cursor[NN];
__device__ int    g_csrc[EE];        // CSR-by-dst: source node per slot
__device__ int    g_bsum[64];

// ---------------- CSR build ----------------
__global__ void k_hist(const int* __restrict__ dst) {
    int e = blockIdx.x * blockDim.x + threadIdx.x;
    if (e < EE) atomicAdd(&g_deg[dst[e]], 1);
}

__global__ void __launch_bounds__(1024) k_scan1() {
    __shared__ int ws[32];
    int i = blockIdx.x * 1024 + threadIdx.x;
    int lane = threadIdx.x & 31, w = threadIdx.x >> 5;
    int x = (i < NN) ? g_deg[i] : 0;
    int v = x;
#pragma unroll
    for (int o = 1; o < 32; o <<= 1) {
        int t = __shfl_up_sync(0xffffffffu, v, o);
        if (lane >= o) v += t;
    }
    if (lane == 31) ws[w] = v;
    __syncthreads();
    if (w == 0) {
        int t = ws[lane];
#pragma unroll
        for (int o = 1; o < 32; o <<= 1) {
            int u = __shfl_up_sync(0xffffffffu, t, o);
            if (lane >= o) t += u;
        }
        ws[lane] = t;
    }
    __syncthreads();
    int off = (w > 0) ? ws[w - 1] : 0;
    int incl = v + off;
    if (i < NN) g_rowptr[i] = incl - x;           // exclusive within block
    if (threadIdx.x == 1023) g_bsum[blockIdx.x] = incl;  // inclusive block total
}

// adds block-prefix (computed in-block from g_bsum) and inits cursor
__global__ void __launch_bounds__(256) k_scan3() {
    __shared__ int carry_s;
    int chunkId = (blockIdx.x * 256) >> 10;       // which scan1 block we're in
    if (threadIdx.x < 32) {
        int v = 0;
        if (threadIdx.x < chunkId) v = g_bsum[threadIdx.x];
        int b2 = threadIdx.x + 32;
        if (b2 < chunkId) v += g_bsum[b2];
#pragma unroll
        for (int o = 16; o > 0; o >>= 1) v += __shfl_xor_sync(0xffffffffu, v, o);
        if (threadIdx.x == 0) carry_s = v;
    }
    __syncthreads();
    int i = blockIdx.x * 256 + threadIdx.x;
    if (i < NN) {
        int r = g_rowptr[i] + carry_s;
        g_rowptr[i] = r;
        g_cursor[i] = r;
    }
    if (i == 0) g_rowptr[NN] = EE;
}

__global__ void k_scatter(const int* __restrict__ src, const int* __restrict__ dst) {
    int e = blockIdx.x * blockDim.x + threadIdx.x;
    if (e < EE) {
        int pos = atomicAdd(&g_cursor[dst[e]], 1);
        g_csrc[pos] = src[e];
    }
}

// ---------------- split-fp16 tensor GEMM (packed-K Markidis) ----------------
// C = A@W + bias with ~fp32 precision: A=Ah+Al, W=Wh+Wl (fp16 splits);
// C = Ah*Wh + Al*Wh + Ah*Wl (+O(2^-22)). Packed as As=[Ah|Al] (64x128) and
// Bs=[Wh;Wl] (128x64); a 12-step (a_kk,b_kk) pairing covers the 3 products.
// Block 128 thr / 64 rows; warp tile m16 x n64. smem 36KB (same as plain fp16).
// att mode: writes half hp + fused per-head att dots ai (fp32) / aj (fp16).
// relu mode: writes fp32 Cf (input embedding).
__device__ __forceinline__ uint32_t smem_u32(const void* p) {
    return (uint32_t)__cvta_generic_to_shared(p);
}

#define LDSM_X4(r0, r1, r2, r3, addr) \
    asm volatile("ldmatrix.sync.aligned.m8n8.x4.shared.b16 {%0,%1,%2,%3}, [%4];" \
        : "=r"(r0), "=r"(r1), "=r"(r2), "=r"(r3) : "r"(addr))

#define LDSM_X4_T(r0, r1, r2, r3, addr) \
    asm volatile("ldmatrix.sync.aligned.m8n8.x4.trans.shared.b16 {%0,%1,%2,%3}, [%4];" \
        : "=r"(r0), "=r"(r1), "=r"(r2), "=r"(r3) : "r"(addr))

#define MMA16816(c, a0, a1, a2, a3, b0, b1) \
    asm volatile("mma.sync.aligned.m16n8k16.row.col.f32.f16.f16.f32 " \
        "{%0,%1,%2,%3}, {%4,%5,%6,%7}, {%8,%9}, {%0,%1,%2,%3};" \
        : "+f"(c[0]), "+f"(c[1]), "+f"(c[2]), "+f"(c[3]) \
        : "r"(a0), "r"(a1), "r"(a2), "r"(a3), "r"(b0), "r"(b1))

#define SMSA 136  // As row stride in halves (128 + 8 pad)
#define SMSB 72   // Bs row stride in halves (64 + 8 pad)

__device__ __forceinline__ void split8(const float* v, __half* hi, __half* lo) {
#pragma unroll
    for (int q = 0; q < 8; q++) {
        __half h = __float2half_rn(v[q]);
        hi[q] = h;
        lo[q] = __float2half_rn(v[q] - __half2float(h));
    }
}

__global__ void __launch_bounds__(128) k_gemm_s(const float* __restrict__ A,
                                                const float* __restrict__ W,
                                                const float* __restrict__ bias,
                                                float* __restrict__ Cf,
                                                __half* __restrict__ Ch,
                                                int do_relu,
                                                const float* __restrict__ att) {
    __shared__ __half As[64 * SMSA];   // [Ah | Al]
    __shared__ __half Bs[128 * SMSB];  // [Wh ; Wl]
    int tid = threadIdx.x;
    int base = blockIdx.x * 64;
#pragma unroll
    for (int i = 0; i < 4; i++) {
        int chunk = tid + i * 128;            // 0..511
        int r = chunk >> 3, c = (chunk & 7) * 8;
        float wv[8];
        *(float4*)(wv)     = *(const float4*)(W + r * 64 + c);
        *(float4*)(wv + 4) = *(const float4*)(W + r * 64 + c + 4);
        __align__(16) __half wh[8], wl[8];
        split8(wv, wh, wl);
        *(uint4*)(Bs + r * SMSB + c)          = *(uint4*)wh;
        *(uint4*)(Bs + (64 + r) * SMSB + c)   = *(uint4*)wl;

        int gr = base + r;
        float av[8] = {0.f, 0.f, 0.f, 0.f, 0.f, 0.f, 0.f, 0.f};
        if (gr < NN) {
            *(float4*)(av)     = *(const float4*)(A + (size_t)gr * 64 + c);
            *(float4*)(av + 4) = *(const float4*)(A + (size_t)gr * 64 + c + 4);
        }
        __align__(16) __half ah[8], al[8];
        split8(av, ah, al);
        *(uint4*)(As + r * SMSA + c)        = *(uint4*)ah;
        *(uint4*)(As + r * SMSA + c + 64)   = *(uint4*)al;
    }
    __syncthreads();

    int warp = tid >> 5, lane = tid & 31;
    int m0 = warp * 16;
    float acc[8][4];
#pragma unroll
    for (int n = 0; n < 8; n++)
#pragma unroll
        for (int q = 0; q < 4; q++) acc[n][q] = 0.f;

    // preload all A fragments: ka 0..3 = Ah, 4..7 = Al
    uint32_t aA[8][4];
#pragma unroll
    for (int ka = 0; ka < 8; ka++) {
        int aoff = (m0 + (lane & 15)) * SMSA + ka * 16 + (lane >> 4) * 8;
        LDSM_X4(aA[ka][0], aA[ka][1], aA[ka][2], aA[ka][3], smem_u32(As + aoff));
    }

#pragma unroll
    for (int np = 0; np < 4; np++) {
        // b rows 0..3 = Wh: used with Ah (term1) and Al (term2)
#pragma unroll
        for (int kk = 0; kk < 4; kk++) {
            uint32_t b0, b1, b2, b3;
            int boff = (kk * 16 + (lane & 15)) * SMSB + np * 16 + (lane >> 4) * 8;
            LDSM_X4_T(b0, b1, b2, b3, smem_u32(Bs + boff));
            MMA16816(acc[2 * np],     aA[kk][0], aA[kk][1], aA[kk][2], aA[kk][3], b0, b1);
            MMA16816(acc[2 * np + 1], aA[kk][0], aA[kk][1], aA[kk][2], aA[kk][3], b2, b3);
            MMA16816(acc[2 * np],     aA[kk + 4][0], aA[kk + 4][1], aA[kk + 4][2], aA[kk + 4][3], b0, b1);
            MMA16816(acc[2 * np + 1], aA[kk + 4][0], aA[kk + 4][1], aA[kk + 4][2], aA[kk + 4][3], b2, b3);
        }
        // b rows 4..7 = Wl: used with Ah (term3)
#pragma unroll
        for (int kk = 0; kk < 4; kk++) {
            uint32_t b0, b1, b2, b3;
            int boff = ((kk + 4) * 16 + (lane & 15)) * SMSB + np * 16 + (lane >> 4) * 8;
            LDSM_X4_T(b0, b1, b2, b3, smem_u32(Bs + boff));
            MMA16816(acc[2 * np],     aA[kk][0], aA[kk][1], aA[kk][2], aA[kk][3], b0, b1);
            MMA16816(acc[2 * np + 1], aA[kk][0], aA[kk][1], aA[kk][2], aA[kk][3], b2, b3);
        }
    }

    int qr = lane >> 2, qc = (lane & 3) * 2;
    int r0 = base + m0 + qr, r1 = r0 + 8;
    if (att != nullptr) {
#pragma unroll
        for (int n = 0; n < 8; n++) {
            int col = n * 8 + qc;
            float2 bb = *(const float2*)(bias + col);
            float x0 = acc[n][0] + bb.x, y0 = acc[n][1] + bb.y;
            float x1 = acc[n][2] + bb.x, y1 = acc[n][3] + bb.y;
            // head index == n; this thread covers cols qc, qc+1 of head n
            float ci0 = att[n * 16 + qc],     ci1 = att[n * 16 + qc + 1];
            float cj0 = att[n * 16 + 8 + qc], cj1 = att[n * 16 + 8 + qc + 1];
            float pi0 = x0 * ci0 + y0 * ci1, pj0 = x0 * cj0 + y0 * cj1;
            float pi1 = x1 * ci0 + y1 * ci1, pj1 = x1 * cj0 + y1 * cj1;
            pi0 += __shfl_xor_sync(0xffffffffu, pi0, 1);
            pi0 += __shfl_xor_sync(0xffffffffu, pi0, 2);
            pj0 += __shfl_xor_sync(0xffffffffu, pj0, 1);
            pj0 += __shfl_xor_sync(0xffffffffu, pj0, 2);
            pi1 += __shfl_xor_sync(0xffffffffu, pi1, 1);
            pi1 += __shfl_xor_sync(0xffffffffu, pi1, 2);
            pj1 += __shfl_xor_sync(0xffffffffu, pj1, 1);
            pj1 += __shfl_xor_sync(0xffffffffu, pj1, 2);
            if (r0 < NN) {
                *(__half2*)(Ch + (size_t)r0 * 64 + col) = __floats2half2_rn(x0, y0);
                if ((lane & 3) == 0) {
                    g_ai[r0 * 8 + n]  = pi0;
                    g_ajh[r0 * 8 + n] = __float2half(pj0);
                }
            }
            if (r1 < NN) {
                *(__half2*)(Ch + (size_t)r1 * 64 + col) = __floats2half2_rn(x1, y1);
                if ((lane & 3) == 0) {
                    g_ai[r1 * 8 + n]  = pi1;
                    g_ajh[r1 * 8 + n] = __float2half(pj1);
                }
            }
        }
    } else {
#pragma unroll
        for (int n = 0; n < 8; n++) {
            int col = n * 8 + qc;
            float2 bb = *(const float2*)(bias + col);
            float x0 = acc[n][0] + bb.x, y0 = acc[n][1] + bb.y;
            float x1 = acc[n][2] + bb.x, y1 = acc[n][3] + bb.y;
            if (do_relu) {
                x0 = fmaxf(x0, 0.f); y0 = fmaxf(y0, 0.f);
                x1 = fmaxf(x1, 0.f); y1 = fmaxf(y1, 0.f);
            }
            if (r0 < NN) *(float2*)(Cf + (size_t)r0 * 64 + col) = make_float2(x0, y0);
            if (r1 < NN) *(float2*)(Cf + (size_t)r1 * 64 + col) = make_float2(x1, y1);
        }
    }
}

// ---------------- fused edge softmax + aggregation + ELU + LayerNorm ----------------
// One warp per destination node. Lane l owns cols (2l,2l+1), head h = l>>2.
// Single-pass shift-free softmax; src indices preloaded coalesced + shuffled;
// 4-way unrolled gathers (fp16 features + fp16 aj). Output fp32.
__global__ void __launch_bounds__(256) k_edge(const float* __restrict__ ob,
                                              const float* __restrict__ lg,
                                              const float* __restrict__ lb,
                                              float* __restrict__ out) {
    int n = (blockIdx.x * blockDim.x + threadIdx.x) >> 5;
    int lane = threadIdx.x & 31;
    if (n >= NN) return;
    int e0 = __ldg(&g_rowptr[n]), e1 = __ldg(&g_rowptr[n + 1]);
    int h = lane >> 2;
    float aih = __ldg(&g_ai[n * 8 + h]);

    float s = 0.f, ax = 0.f, ay = 0.f;
    const __half2* hp2 = (const __half2*)g_hph;
    for (int cb = e0; cb < e1; cb += 32) {
        int idx = cb + lane;
        int pre = (idx < e1) ? __ldg(&g_csrc[idx]) : 0;
        int cnt = min(32, e1 - cb);
        int j = 0;
        for (; j + 4 <= cnt; j += 4) {
            int s0 = __shfl_sync(0xffffffffu, pre, j);
            int s1 = __shfl_sync(0xffffffffu, pre, j + 1);
            int s2 = __shfl_sync(0xffffffffu, pre, j + 2);
            int s3 = __shfl_sync(0xffffffffu, pre, j + 3);
            float b0 = __half2float(__ldg(&g_ajh[s0 * 8 + h]));
            float b1 = __half2float(__ldg(&g_ajh[s1 * 8 + h]));
            float b2 = __half2float(__ldg(&g_ajh[s2 * 8 + h]));
            float b3 = __half2float(__ldg(&g_ajh[s3 * 8 + h]));
            __half2 u0 = __ldg(&hp2[(size_t)s0 * 32 + lane]);
            __half2 u1 = __ldg(&hp2[(size_t)s1 * 32 + lane]);
            __half2 u2 = __ldg(&hp2[(size_t)s2 * 32 + lane]);
            __half2 u3 = __ldg(&hp2[(size_t)s3 * 32 + lane]);
            float2 v0 = __half22float2(u0);
            float2 v1 = __half22float2(u1);
            float2 v2 = __half22float2(u2);
            float2 v3 = __half22float2(u3);
            float a0 = aih + b0; a0 = fmaxf(a0, 0.2f * a0); float w0 = __expf(a0);
            float a1 = aih + b1; a1 = fmaxf(a1, 0.2f * a1); float w1 = __expf(a1);
            float a2 = aih + b2; a2 = fmaxf(a2, 0.2f * a2); float w2 = __expf(a2);
            float a3 = aih + b3; a3 = fmaxf(a3, 0.2f * a3); float w3 = __expf(a3);
            s += w0 + w1 + w2 + w3;
            ax += v0.x * w0 + v1.x * w1 + v2.x * w2 + v3.x * w3;
            ay += v0.y * w0 + v1.y * w1 + v2.y * w2 + v3.y * w3;
        }
        for (; j < cnt; j++) {
            int sj = __shfl_sync(0xffffffffu, pre, j);
            float b = __half2float(__ldg(&g_ajh[sj * 8 + h]));
            float2 v = __half22float2(__ldg(&hp2[(size_t)sj * 32 + lane]));
            float a = aih + b; a = fmaxf(a, 0.2f * a); float w = __expf(a);
            s += w;
            ax += v.x * w;
            ay += v.y * w;
        }
    }

    float inv = 1.f / (s + 1e-16f);
    float vx = ax * inv + ob[2 * lane];
    float vy = ay * inv + ob[2 * lane + 1];
    vx = vx > 0.f ? vx : expm1f(vx);          // ELU
    vy = vy > 0.f ? vy : expm1f(vy);

    float sum = vx + vy, sq = vx * vx + vy * vy;
#pragma unroll
    for (int o = 16; o > 0; o >>= 1) {
        sum += __shfl_xor_sync(0xffffffffu, sum, o);
        sq  += __shfl_xor_sync(0xffffffffu, sq, o);
    }
    float mu = sum * (1.f / 64.f);
    float var = sq * (1.f / 64.f) - mu * mu;
    float rstd = rsqrtf(var + 1e-5f);
    float2 o2;
    o2.x = (vx - mu) * rstd * lg[2 * lane] + lb[2 * lane];
    o2.y = (vy - mu) * rstd * lg[2 * lane + 1] + lb[2 * lane + 1];
    ((float2*)out)[(size_t)n * 32 + lane] = o2;
}

// ---------------- launch ----------------
extern "C" void kernel_launch(void* const* d_in, const int* in_sizes, int n_in,
                              void* d_out, int out_size) {
    const float* x        = (const float*)d_in[0];
    const int*   ei       = (const int*)  d_in[1];
    const float* W_in     = (const float*)d_in[2];
    const float* b_in     = (const float*)d_in[3];
    const float* lin_w    = (const float*)d_in[4];
    const float* lin_b    = (const float*)d_in[5];
    const float* att      = (const float*)d_in[6];
    const float* out_bias = (const float*)d_in[7];
    const float* ln_g     = (const float*)d_in[8];
    const float* ln_b     = (const float*)d_in[9];
    float* out = (float*)d_out;
    const int* srcp = ei;        // edge_index[0]
    const int* dstp = ei + EE;   // edge_index[1]
    (void)n_in; (void)in_sizes; (void)out_size;

    void* p;
    cudaGetSymbolAddress(&p, g_h);    float*  ph   = (float*)p;
    cudaGetSymbolAddress(&p, g_hph);  __half* phph = (__half*)p;
    cudaGetSymbolAddress(&p, g_deg);
    cudaMemsetAsync(p, 0, NN * sizeof(int));

    // CSR by dst
    const int nsb = (NN + 1023) / 1024;   // 49
    k_hist   <<<(EE + 255) / 256, 256>>>(dstp);
    k_scan1  <<<nsb, 1024>>>();
    k_scan3  <<<(NN + 255) / 256, 256>>>();
    k_scatter<<<(EE + 255) / 256, 256>>>(srcp, dstp);

    int gblocks = (NN + 63) / 64;
    // input embedding: h = relu(x @ W_in + b_in), fp32
    k_gemm_s<<<gblocks, 128>>>(x, W_in, b_in, ph, nullptr, 1, nullptr);

    for (int l = 0; l < 5; l++) {
        k_gemm_s<<<gblocks, 128>>>(ph, lin_w + l * 64 * 64, lin_b + l * 64,
                                   nullptr, phph, 0, att + l * 128);
        k_edge<<<(NN + 7) / 8, 256>>>(out_bias + l * 64, ln_g + l * 64, ln_b + l * 64,
                                      (l == 4) ? out : ph);
    }
}

// round 10
// speedup vs baseline: 1.1412x; 1.0243x over previous
#include <cuda_runtime.h>
#include <cuda_fp16.h>
#include <math.h>
#include <stdint.h>

#define NN 50000
#define EE 800000
#define DD 64
#define HH 8

// ---------------- scratch (static device globals; no allocation) ----------------
__device__ float  g_h[NN * DD];      // node features fp32 (layer input / ping)
__device__ __half g_hph[NN * DD];    // projected features, half (edge gather)
__device__ float  g_ai[NN * HH];     // per-node att dot, dst half (fp32)
__device__ __half g_ajh[NN * HH];    // per-node att dot, src half (fp16)
__device__ int    g_deg[NN];         // zero at entry (zeroed by input GEMM each call)
__device__ int    g_rowptr[NN];      // after scatter: rowptr[n] == orig rowptr[n+1]
__device__ int    g_csrc[EE];        // CSR-by-dst: source node per slot

// ---------------- CSR build ----------------
__global__ void k_hist(const int* __restrict__ dst) {
    int e = blockIdx.x * blockDim.x + threadIdx.x;
    if (e < EE) atomicAdd(&g_deg[dst[e]], 1);
}

// single merged scan: each block redundantly computes its carry (sum of deg
// before its chunk), then does a local 1024-wide scan and writes rowptr.
__global__ void __launch_bounds__(1024) k_scan() {
    __shared__ int ws[32];
    __shared__ int red[32];
    int tidx = threadIdx.x;
    int lane = tidx & 31, w = tidx >> 5;
    int limit = blockIdx.x << 10;
    // carry = sum deg[0 .. limit)
    int acc = 0;
    for (int i = tidx; i < limit; i += 1024) acc += g_deg[i];
#pragma unroll
    for (int o = 16; o > 0; o >>= 1) acc += __shfl_xor_sync(0xffffffffu, acc, o);
    if (lane == 0) red[w] = acc;
    // local chunk
    int i = limit + tidx;
    int x = (i < NN) ? g_deg[i] : 0;
    int v = x;
#pragma unroll
    for (int o = 1; o < 32; o <<= 1) {
        int t = __shfl_up_sync(0xffffffffu, v, o);
        if (lane >= o) v += t;
    }
    if (lane == 31) ws[w] = v;
    __syncthreads();
    if (w == 0) {
        int t = ws[lane];
#pragma unroll
        for (int o = 1; o < 32; o <<= 1) {
            int u = __shfl_up_sync(0xffffffffu, t, o);
            if (lane >= o) t += u;
        }
        ws[lane] = t;
        int r = red[lane];
#pragma unroll
        for (int o = 16; o > 0; o >>= 1) r += __shfl_xor_sync(0xffffffffu, r, o);
        if (lane == 0) red[0] = r;
    }
    __syncthreads();
    int carry = red[0];
    int off = (w > 0) ? ws[w - 1] : 0;
    if (i < NN) g_rowptr[i] = carry + off + v - x;   // exclusive global prefix
}

__global__ void k_scatter(const int* __restrict__ src, const int* __restrict__ dst) {
    int e = blockIdx.x * blockDim.x + threadIdx.x;
    if (e < EE) {
        int pos = atomicAdd(&g_rowptr[dst[e]], 1);
        g_csrc[pos] = src[e];
    }
}

// ---------------- split-fp16 tensor GEMM (packed-K Markidis) ----------------
// C = A@W + bias with ~fp32 precision: A=Ah+Al, W=Wh+Wl (fp16 splits);
// C = Ah*Wh + Al*Wh + Ah*Wl (+O(2^-22)). As=[Ah|Al] (64x128), Bs=[Wh;Wl] (128x64).
// Block 128 thr / 64 rows; warp tile m16 x n64. smem 36KB.
// att mode: writes half hp + fused per-head att dots ai (fp32) / aj (fp16).
// relu mode: writes fp32 Cf (input embedding) and zeroes g_deg for next call.
__device__ __forceinline__ uint32_t smem_u32(const void* p) {
    return (uint32_t)__cvta_generic_to_shared(p);
}

#define LDSM_X4(r0, r1, r2, r3, addr) \
    asm volatile("ldmatrix.sync.aligned.m8n8.x4.shared.b16 {%0,%1,%2,%3}, [%4];" \
        : "=r"(r0), "=r"(r1), "=r"(r2), "=r"(r3) : "r"(addr))

#define LDSM_X4_T(r0, r1, r2, r3, addr) \
    asm volatile("ldmatrix.sync.aligned.m8n8.x4.trans.shared.b16 {%0,%1,%2,%3}, [%4];" \
        : "=r"(r0), "=r"(r1), "=r"(r2), "=r"(r3) : "r"(addr))

#define MMA16816(c, a0, a1, a2, a3, b0, b1) \
    asm volatile("mma.sync.aligned.m16n8k16.row.col.f32.f16.f16.f32 " \
        "{%0,%1,%2,%3}, {%4,%5,%6,%7}, {%8,%9}, {%0,%1,%2,%3};" \
        : "+f"(c[0]), "+f"(c[1]), "+f"(c[2]), "+f"(c[3]) \
        : "r"(a0), "r"(a1), "r"(a2), "r"(a3), "r"(b0), "r"(b1))

#define SMSA 136  // As row stride in halves (128 + 8 pad)
#define SMSB 72   // Bs row stride in halves (64 + 8 pad)

__device__ __forceinline__ void split8(const float* v, __half* hi, __half* lo) {
#pragma unroll
    for (int q = 0; q < 8; q++) {
        __half h = __float2half_rn(v[q]);
        hi[q] = h;
        lo[q] = __float2half_rn(v[q] - __half2float(h));
    }
}

__global__ void __launch_bounds__(128) k_gemm_s(const float* __restrict__ A,
                                                const float* __restrict__ W,
                                                const float* __restrict__ bias,
                                                float* __restrict__ Cf,
                                                __half* __restrict__ Ch,
                                                int do_relu,
                                                const float* __restrict__ att) {
    __shared__ __half As[64 * SMSA];   // [Ah | Al]
    __shared__ __half Bs[128 * SMSB];  // [Wh ; Wl]
    int tid = threadIdx.x;
    int base = blockIdx.x * 64;
    if (do_relu) {                     // reset deg for the NEXT call's histogram
        int gz = blockIdx.x * 128 + tid;
        if (gz < NN) g_deg[gz] = 0;
    }
#pragma unroll
    for (int i = 0; i < 4; i++) {
        int chunk = tid + i * 128;            // 0..511
        int r = chunk >> 3, c = (chunk & 7) * 8;
        float wv[8];
        *(float4*)(wv)     = *(const float4*)(W + r * 64 + c);
        *(float4*)(wv + 4) = *(const float4*)(W + r * 64 + c + 4);
        __align__(16) __half wh[8], wl[8];
        split8(wv, wh, wl);
        *(uint4*)(Bs + r * SMSB + c)          = *(uint4*)wh;
        *(uint4*)(Bs + (64 + r) * SMSB + c)   = *(uint4*)wl;

        int gr = base + r;
        float av[8] = {0.f, 0.f, 0.f, 0.f, 0.f, 0.f, 0.f, 0.f};
        if (gr < NN) {
            *(float4*)(av)     = *(const float4*)(A + (size_t)gr * 64 + c);
            *(float4*)(av + 4) = *(const float4*)(A + (size_t)gr * 64 + c + 4);
        }
        __align__(16) __half ah[8], al[8];
        split8(av, ah, al);
        *(uint4*)(As + r * SMSA + c)        = *(uint4*)ah;
        *(uint4*)(As + r * SMSA + c + 64)   = *(uint4*)al;
    }
    __syncthreads();

    int warp = tid >> 5, lane = tid & 31;
    int m0 = warp * 16;
    float acc[8][4];
#pragma unroll
    for (int n = 0; n < 8; n++)
#pragma unroll
        for (int q = 0; q < 4; q++) acc[n][q] = 0.f;

    // preload all A fragments: ka 0..3 = Ah, 4..7 = Al
    uint32_t aA[8][4];
#pragma unroll
    for (int ka = 0; ka < 8; ka++) {
        int aoff = (m0 + (lane & 15)) * SMSA + ka * 16 + (lane >> 4) * 8;
        LDSM_X4(aA[ka][0], aA[ka][1], aA[ka][2], aA[ka][3], smem_u32(As + aoff));
    }

#pragma unroll
    for (int np = 0; np < 4; np++) {
        // b rows 0..3 = Wh: paired with Ah (term1) and Al (term2)
#pragma unroll
        for (int kk = 0; kk < 4; kk++) {
            uint32_t b0, b1, b2, b3;
            int boff = (kk * 16 + (lane & 15)) * SMSB + np * 16 + (lane >> 4) * 8;
            LDSM_X4_T(b0, b1, b2, b3, smem_u32(Bs + boff));
            MMA16816(acc[2 * np],     aA[kk][0], aA[kk][1], aA[kk][2], aA[kk][3], b0, b1);
            MMA16816(acc[2 * np + 1], aA[kk][0], aA[kk][1], aA[kk][2], aA[kk][3], b2, b3);
            MMA16816(acc[2 * np],     aA[kk + 4][0], aA[kk + 4][1], aA[kk + 4][2], aA[kk + 4][3], b0, b1);
            MMA16816(acc[2 * np + 1], aA[kk + 4][0], aA[kk + 4][1], aA[kk + 4][2], aA[kk + 4][3], b2, b3);
        }
        // b rows 4..7 = Wl: paired with Ah (term3)
#pragma unroll
        for (int kk = 0; kk < 4; kk++) {
            uint32_t b0, b1, b2, b3;
            int boff = ((kk + 4) * 16 + (lane & 15)) * SMSB + np * 16 + (lane >> 4) * 8;
            LDSM_X4_T(b0, b1, b2, b3, smem_u32(Bs + boff));
            MMA16816(acc[2 * np],     aA[kk][0], aA[kk][1], aA[kk][2], aA[kk][3], b0, b1);
            MMA16816(acc[2 * np + 1], aA[kk][0], aA[kk][1], aA[kk][2], aA[kk][3], b2, b3);
        }
    }

    int qr = lane >> 2, qc = (lane & 3) * 2;
    int r0 = base + m0 + qr, r1 = r0 + 8;
    if (att != nullptr) {
#pragma unroll
        for (int n = 0; n < 8; n++) {
            int col = n * 8 + qc;
            float2 bb = *(const float2*)(bias + col);
            float x0 = acc[n][0] + bb.x, y0 = acc[n][1] + bb.y;
            float x1 = acc[n][2] + bb.x, y1 = acc[n][3] + bb.y;
            // head index == n; this thread covers cols qc, qc+1 of head n
            float ci0 = att[n * 16 + qc],     ci1 = att[n * 16 + qc + 1];
            float cj0 = att[n * 16 + 8 + qc], cj1 = att[n * 16 + 8 + qc + 1];
            float pi0 = x0 * ci0 + y0 * ci1, pj0 = x0 * cj0 + y0 * cj1;
            float pi1 = x1 * ci0 + y1 * ci1, pj1 = x1 * cj0 + y1 * cj1;
            pi0 += __shfl_xor_sync(0xffffffffu, pi0, 1);
            pi0 += __shfl_xor_sync(0xffffffffu, pi0, 2);
            pj0 += __shfl_xor_sync(0xffffffffu, pj0, 1);
            pj0 += __shfl_xor_sync(0xffffffffu, pj0, 2);
            pi1 += __shfl_xor_sync(0xffffffffu, pi1, 1);
            pi1 += __shfl_xor_sync(0xffffffffu, pi1, 2);
            pj1 += __shfl_xor_sync(0xffffffffu, pj1, 1);
            pj1 += __shfl_xor_sync(0xffffffffu, pj1, 2);
            if (r0 < NN) {
                *(__half2*)(Ch + (size_t)r0 * 64 + col) = __floats2half2_rn(x0, y0);
                if ((lane & 3) == 0) {
                    g_ai[r0 * 8 + n]  = pi0;
                    g_ajh[r0 * 8 + n] = __float2half(pj0);
                }
            }
            if (r1 < NN) {
                *(__half2*)(Ch + (size_t)r1 * 64 + col) = __floats2half2_rn(x1, y1);
                if ((lane & 3) == 0) {
                    g_ai[r1 * 8 + n]  = pi1;
                    g_ajh[r1 * 8 + n] = __float2half(pj1);
                }
            }
        }
    } else {
#pragma unroll
        for (int n = 0; n < 8; n++) {
            int col = n * 8 + qc;
            float2 bb = *(const float2*)(bias + col);
            float x0 = acc[n][0] + bb.x, y0 = acc[n][1] + bb.y;
            float x1 = acc[n][2] + bb.x, y1 = acc[n][3] + bb.y;
            if (do_relu) {
                x0 = fmaxf(x0, 0.f); y0 = fmaxf(y0, 0.f);
                x1 = fmaxf(x1, 0.f); y1 = fmaxf(y1, 0.f);
            }
            if (r0 < NN) *(float2*)(Cf + (size_t)r0 * 64 + col) = make_float2(x0, y0);
            if (r1 < NN) *(float2*)(Cf + (size_t)r1 * 64 + col) = make_float2(x1, y1);
        }
    }
}

// ---------------- fused edge softmax + aggregation + ELU + LayerNorm ----------------
// One warp per destination node. Lane l owns cols (2l,2l+1), head h = l>>2.
// Per group of 4 edges, the 32 lanes cover exactly 4 edges x 8 heads: lane L
// loads aj for (edge g4+(L&3), head L>>2), computes ONE lrelu+exp, and weights
// are distributed via shfl (per-lane source index). 4x fewer MUFU/aj-loads than
// per-lane recompute. Next group's aj is prefetched. Output fp32.
__global__ void __launch_bounds__(256) k_edge(const float* __restrict__ ob,
                                              const float* __restrict__ lg,
                                              const float* __restrict__ lb,
                                              float* __restrict__ out) {
    int n = (blockIdx.x * blockDim.x + threadIdx.x) >> 5;
    int lane = threadIdx.x & 31;
    if (n >= NN) return;
    // post-scatter rowptr is shifted: rp[n] == original rowptr[n+1]
    int e0 = (n == 0) ? 0 : __ldg(&g_rowptr[n - 1]);
    int e1 = __ldg(&g_rowptr[n]);
    int h = lane >> 2;
    int sub = lane & 3;        // my edge slot within a group
    int qb = lane & ~3;        // quad base lane (holds my head's 4 edge weights)
    float aih = __ldg(&g_ai[n * 8 + h]);

    float s = 0.f, ax = 0.f, ay = 0.f;
    const __half2* hp2 = (const __half2*)g_hph;
    for (int cb = e0; cb < e1; cb += 32) {
        int idx = cb + lane;
        int pre = (idx < e1) ? __ldg(&g_csrc[idx]) : 0;
        int cnt = min(32, e1 - cb);
        int ng = (cnt + 3) >> 2;
        // prefetch group 0's aj value for (edge sub, head h)
        int srcv = __shfl_sync(0xffffffffu, pre, sub);
        __half ajv = __ldg(&g_ajh[srcv * 8 + h]);
        for (int g = 0; g < ng; g++) {
            int ecur = g * 4 + sub;
            float av = __half2float(ajv);
            if (g + 1 < ng) {                 // prefetch next group's aj
                int srcn = __shfl_sync(0xffffffffu, pre, ecur + 4);
                ajv = __ldg(&g_ajh[srcn * 8 + h]);
            }
            float a = aih + av;
            a = fmaxf(a, 0.2f * a);           // leaky_relu(0.2)
            float wv = (ecur < cnt) ? __expf(a) : 0.f;
            int s0 = __shfl_sync(0xffffffffu, pre, g * 4);
            int s1 = __shfl_sync(0xffffffffu, pre, g * 4 + 1);
            int s2 = __shfl_sync(0xffffffffu, pre, g * 4 + 2);
            int s3 = __shfl_sync(0xffffffffu, pre, g * 4 + 3);
            float2 v0 = __half22float2(__ldg(&hp2[(size_t)s0 * 32 + lane]));
            float2 v1 = __half22float2(__ldg(&hp2[(size_t)s1 * 32 + lane]));
            float2 v2 = __half22float2(__ldg(&hp2[(size_t)s2 * 32 + lane]));
            float2 v3 = __half22float2(__ldg(&hp2[(size_t)s3 * 32 + lane]));
            float w0 = __shfl_sync(0xffffffffu, wv, qb);
            float w1 = __shfl_sync(0xffffffffu, wv, qb + 1);
            float w2 = __shfl_sync(0xffffffffu, wv, qb + 2);
            float w3 = __shfl_sync(0xffffffffu, wv, qb + 3);
            s += w0 + w1 + w2 + w3;
            ax += v0.x * w0 + v1.x * w1 + v2.x * w2 + v3.x * w3;
            ay += v0.y * w0 + v1.y * w1 + v2.y * w2 + v3.y * w3;
        }
    }

    float inv = 1.f / (s + 1e-16f);
    float vx = ax * inv + ob[2 * lane];
    float vy = ay * inv + ob[2 * lane + 1];
    vx = vx > 0.f ? vx : expm1f(vx);          // ELU
    vy = vy > 0.f ? vy : expm1f(vy);

    float sum = vx + vy, sq = vx * vx + vy * vy;
#pragma unroll
    for (int o = 16; o > 0; o >>= 1) {
        sum += __shfl_xor_sync(0xffffffffu, sum, o);
        sq  += __shfl_xor_sync(0xffffffffu, sq, o);
    }
    float mu = sum * (1.f / 64.f);
    float var = sq * (1.f / 64.f) - mu * mu;
    float rstd = rsqrtf(var + 1e-5f);
    float2 o2;
    o2.x = (vx - mu) * rstd * lg[2 * lane] + lb[2 * lane];
    o2.y = (vy - mu) * rstd * lg[2 * lane + 1] + lb[2 * lane + 1];
    ((float2*)out)[(size_t)n * 32 + lane] = o2;
}

// ---------------- launch ----------------
extern "C" void kernel_launch(void* const* d_in, const int* in_sizes, int n_in,
                              void* d_out, int out_size) {
    const float* x        = (const float*)d_in[0];
    const int*   ei       = (const int*)  d_in[1];
    const float* W_in     = (const float*)d_in[2];
    const float* b_in     = (const float*)d_in[3];
    const float* lin_w    = (const float*)d_in[4];
    const float* lin_b    = (const float*)d_in[5];
    const float* att      = (const float*)d_in[6];
    const float* out_bias = (const float*)d_in[7];
    const float* ln_g     = (const float*)d_in[8];
    const float* ln_b     = (const float*)d_in[9];
    float* out = (float*)d_out;
    const int* srcp = ei;        // edge_index[0]
    const int* dstp = ei + EE;   // edge_index[1]
    (void)n_in; (void)in_sizes; (void)out_size;

    void* p;
    cudaGetSymbolAddress(&p, g_h);    float*  ph   = (float*)p;
    cudaGetSymbolAddress(&p, g_hph);  __half* phph = (__half*)p;

    // CSR by dst (g_deg is zero at entry: initially zero-filled, and the input
    // GEMM of every call re-zeroes it after k_scan's last read)
    const int nsb = (NN + 1023) / 1024;   // 49
    k_hist   <<<(EE + 255) / 256, 256>>>(dstp);
    k_scan   <<<nsb, 1024>>>();
    k_scatter<<<(EE + 255) / 256, 256>>>(srcp, dstp);

    int gblocks = (NN + 63) / 64;
    // input embedding: h = relu(x @ W_in + b_in), fp32 (also zeroes g_deg)
    k_gemm_s<<<gblocks, 128>>>(x, W_in, b_in, ph, nullptr, 1, nullptr);

    for (int l = 0; l < 5; l++) {
        k_gemm_s<<<gblocks, 128>>>(ph, lin_w + l * 64 * 64, lin_b + l * 64,
                                   nullptr, phph, 0, att + l * 128);
        k_edge<<<(NN + 7) / 8, 256>>>(out_bias + l * 64, ln_g + l * 64, ln_b + l * 64,
                                      (l == 4) ? out : ph);
    }
}